// round 1
// baseline (speedup 1.0000x reference)
#include <cuda_runtime.h>
#include <cuda_bf16.h>
#include <math.h>

// Problem dims
#define Bv 128
#define Lv 512
#define Dv 512
#define Ev 64
#define Hv 512
#define Vv 17

#define FULLMASK 0xffffffffu

// Output layout (float32 concat of the 4 reference outputs)
#define OFF_LOGITS 0
#define OFF_PREDS  (Bv*Lv*Vv)                 // 1114112
#define OFF_PROBS  (OFF_PREDS + Bv*Lv)        // 1179648
#define OFF_EMB    (OFF_PROBS + Bv*Lv*Vv)     // 2293760

// Scratch: pre[b, t, h] = inputs[b,t,:] @ W1[:, :D]^T + b1   (128 MB)
__device__ float g_pre[(size_t)Bv * Lv * Hv];

// ---------------------------------------------------------------------------
// Kernel 1: pre = A @ W1x^T + b1.  A: [M=65536, 512] row-major,
// W1: [512, 576] row-major (use first 512 cols).  NT-GEMM, fp32.
// 128x128 tile, BK=16, 256 threads, 8x8 per-thread microtile.
// ---------------------------------------------------------------------------
__global__ __launch_bounds__(256) void gemm_pre_kernel(
    const float* __restrict__ A, const float* __restrict__ W,
    const float* __restrict__ bias)
{
    constexpr int BM = 128, BN = 128, BK = 16;
    __shared__ float sA[BK][BM + 4];
    __shared__ float sB[BK][BN + 4];

    const int bm = blockIdx.y * BM;
    const int bn = blockIdx.x * BN;
    const int tid = threadIdx.x;
    const int tx = tid & 15;       // N direction
    const int ty = tid >> 4;       // M direction

    float acc[8][8];
#pragma unroll
    for (int i = 0; i < 8; i++)
#pragma unroll
        for (int j = 0; j < 8; j++) acc[i][j] = 0.f;

    for (int k0 = 0; k0 < Dv; k0 += BK) {
#pragma unroll
        for (int s = 0; s < 2; s++) {
            int slot = tid + s * 256;            // 0..511
            int r  = slot >> 2;                  // 0..127
            int c4 = (slot & 3) * 4;             // 0,4,8,12
            float4 va = *reinterpret_cast<const float4*>(
                &A[(size_t)(bm + r) * Dv + k0 + c4]);
            sA[c4 + 0][r] = va.x; sA[c4 + 1][r] = va.y;
            sA[c4 + 2][r] = va.z; sA[c4 + 3][r] = va.w;
            float4 vb = *reinterpret_cast<const float4*>(
                &W[(size_t)(bn + r) * (Dv + Ev) + k0 + c4]);
            sB[c4 + 0][r] = vb.x; sB[c4 + 1][r] = vb.y;
            sB[c4 + 2][r] = vb.z; sB[c4 + 3][r] = vb.w;
        }
        __syncthreads();
#pragma unroll
        for (int k = 0; k < BK; k++) {
            float a[8], b[8];
#pragma unroll
            for (int i = 0; i < 8; i++) a[i] = sA[k][ty * 8 + i];
#pragma unroll
            for (int j = 0; j < 8; j++) b[j] = sB[k][tx * 8 + j];
#pragma unroll
            for (int i = 0; i < 8; i++)
#pragma unroll
                for (int j = 0; j < 8; j++) acc[i][j] += a[i] * b[j];
        }
        __syncthreads();
    }

    float bb[8];
#pragma unroll
    for (int j = 0; j < 8; j++) bb[j] = bias[bn + tx * 8 + j];

#pragma unroll
    for (int i = 0; i < 8; i++) {
        size_t row = (size_t)(bm + ty * 8 + i);
#pragma unroll
        for (int j = 0; j < 8; j += 4) {
            int col = bn + tx * 8 + j;
            float4 v;
            v.x = acc[i][j + 0] + bb[j + 0];
            v.y = acc[i][j + 1] + bb[j + 1];
            v.z = acc[i][j + 2] + bb[j + 2];
            v.w = acc[i][j + 3] + bb[j + 3];
            *reinterpret_cast<float4*>(&g_pre[row * Hv + col]) = v;
        }
    }
}

// ---------------------------------------------------------------------------
// Kernel 2: per-batch sequential scan. 1 CTA per batch element, 544 threads
// (17 warps). Recurrent term is a 17-row table lookup M[pred] in SMEM.
// ---------------------------------------------------------------------------
__global__ __launch_bounds__(544) void scan_kernel(
    const float* __restrict__ emb_table,   // [V, E]
    const float* __restrict__ W1,          // [H, D+E]
    const float* __restrict__ W2,          // [V, H]
    const float* __restrict__ b2,          // [V]
    float* __restrict__ out)
{
    __shared__ float sM[Vv][Hv];     // table @ W1e^T  (34816 B)
    __shared__ float sTab[Vv][Ev];   // zero-padded embedding table (4352 B)
    __shared__ float sH[Hv];         // hidden state (2048 B)
    __shared__ float sLogit[Vv];
    __shared__ int   sPred;

    const int b    = blockIdx.x;
    const int tid  = threadIdx.x;
    const int w    = tid >> 5;
    const int lane = tid & 31;

    // Precompute M[v][h] = sum_e table[v][e] * W1[h][D+e]; row 0 forced zero (padding_idx)
    for (int idx = tid; idx < Vv * Hv; idx += 544) {
        int v = idx / Hv, h = idx - v * Hv;
        float acc = 0.f;
        if (v != 0) {
            const float* er = emb_table + v * Ev;
            const float* wr = W1 + (size_t)h * (Dv + Ev) + Dv;
#pragma unroll 8
            for (int e = 0; e < Ev; e++) acc += er[e] * wr[e];
        }
        sM[v][h] = acc;
    }
    for (int idx = tid; idx < Vv * Ev; idx += 544) {
        int v = idx / Ev, e = idx - v * Ev;
        sTab[v][e] = (v == 0) ? 0.f : emb_table[v * Ev + e];
    }

    // W2 rows in registers: warp w owns logit w; lane holds W2[w][k*32+lane]
    float w2r[16];
    float bias2 = 0.f;
    if (w < Vv) {
#pragma unroll
        for (int k = 0; k < 16; k++) w2r[k] = W2[(size_t)w * Hv + k * 32 + lane];
        bias2 = b2[w];
    }
    __syncthreads();

    float* outL  = out + OFF_LOGITS;
    float* outP  = out + OFF_PREDS;
    float* outQ  = out + OFF_PROBS;
    float* outEb = out + OFF_EMB;

    const float* preB = g_pre + (size_t)b * Lv * Hv;

    int pred = 0;  // PAD
    float pcur = (tid < Hv) ? preB[tid] : 0.f;

    for (int t = 0; t < Lv; t++) {
        // prefetch next step's pre slice
        float pnxt = 0.f;
        if (tid < Hv && t + 1 < Lv) pnxt = preB[(size_t)(t + 1) * Hv + tid];

        if (tid < Hv) sH[tid] = tanhf(pcur + sM[pred][tid]);
        __syncthreads();

        // logits: warp w computes logit[w] = sH . W2[w] + b2[w]
        if (w < Vv) {
            float acc = 0.f;
#pragma unroll
            for (int k = 0; k < 16; k++) acc += sH[k * 32 + lane] * w2r[k];
#pragma unroll
            for (int off = 16; off; off >>= 1)
                acc += __shfl_down_sync(FULLMASK, acc, off);
            if (lane == 0) sLogit[w] = acc + bias2;
        }
        __syncthreads();

        // warp 0: log-softmax + argmax over 17
        if (w == 0) {
            float v  = (lane < Vv) ? sLogit[lane] : -1e30f;
            int   bi = (lane < Vv) ? lane : Vv;
            float bv = v;
#pragma unroll
            for (int off = 16; off; off >>= 1) {
                float ov = __shfl_down_sync(FULLMASK, bv, off);
                int   oi = __shfl_down_sync(FULLMASK, bi, off);
                if (ov > bv || (ov == bv && oi < bi)) { bv = ov; bi = oi; }
            }
            bv = __shfl_sync(FULLMASK, bv, 0);
            bi = __shfl_sync(FULLMASK, bi, 0);
            float e = (lane < Vv) ? expf(v - bv) : 0.f;
            float s = e;
#pragma unroll
            for (int off = 16; off; off >>= 1)
                s += __shfl_down_sync(FULLMASK, s, off);
            s = __shfl_sync(FULLMASK, s, 0);
            float lse = bv + logf(s);
            if (lane < Vv) {
                size_t base = ((size_t)b * Lv + t) * Vv + lane;
                outL[base] = v;
                outQ[base] = v - lse;
            }
            if (lane == 0) {
                sPred = bi;
                outP[(size_t)b * Lv + t] = (float)bi;
            }
        }
        __syncthreads();
        pred = sPred;

        if (tid < Ev)
            outEb[((size_t)b * Lv + t) * Ev + tid] = sTab[pred][tid];

        pcur = pnxt;
    }
}

// ---------------------------------------------------------------------------
extern "C" void kernel_launch(void* const* d_in, const int* in_sizes, int n_in,
                              void* d_out, int out_size)
{
    const float* inputs    = (const float*)d_in[0];  // [B, L, D]
    const float* emb_table = (const float*)d_in[1];  // [V, E]
    const float* W1        = (const float*)d_in[2];  // [H, D+E]
    const float* b1        = (const float*)d_in[3];  // [H]
    const float* W2        = (const float*)d_in[4];  // [V, H]
    const float* b2        = (const float*)d_in[5];  // [V]
    float* out = (float*)d_out;

    (void)in_sizes; (void)n_in; (void)out_size;

    // pre = inputs @ W1[:, :D]^T + b1   over M = B*L rows
    dim3 ggrid(Hv / 128, (Bv * Lv) / 128);   // (4, 512)
    gemm_pre_kernel<<<ggrid, 256>>>(inputs, W1, b1);

    // sequential scan, one CTA per batch element
    scan_kernel<<<Bv, 544>>>(emb_table, W1, W2, b2, out);
}